// round 4
// baseline (speedup 1.0000x reference)
#include <cuda_runtime.h>

#define NC    91
#define CM1   90
#define BIMG  8
#define DET   100
#define NBINS 4096
#define CAP   4096
#define MAXP  4096
#define MAXN  (BIMG*MAXP)
#define NBLK  148
#define NTHR  1024
#define CHROWS 128                      // rows per staged chunk
#define CHF    (CHROWS*NC)              // floats per chunk = 11648 (div by 4)
#define CHF4   (CHF/4)                  // 2912

// ---------- scratch (static device globals) ----------
__device__ float    g_keyoff[MAXN];
__device__ unsigned g_cksort[MAXN];
__device__ unsigned g_hist[BIMG][NBINS];
__device__ unsigned g_cnt[BIMG];
__device__ unsigned long long g_cand[BIMG][CAP];
__device__ int      g_selp[BIMG][DET];
__device__ unsigned g_bar_cnt;
__device__ unsigned g_bar_gen;

__device__ __forceinline__ unsigned f2sort(float x) {
    unsigned u = __float_as_uint(x);
    return (u & 0x80000000u) ? ~u : (u | 0x80000000u);
}

__device__ __forceinline__ void grid_barrier() {
    __syncthreads();
    if (threadIdx.x == 0) {
        __threadfence();
        unsigned gen = *((volatile unsigned*)&g_bar_gen);
        unsigned arrived = atomicAdd(&g_bar_cnt, 1u);
        if (arrived == (unsigned)(gridDim.x - 1)) {
            g_bar_cnt = 0;
            __threadfence();
            atomicExch(&g_bar_gen, gen + 1u);
        } else {
            while (*((volatile unsigned*)&g_bar_gen) == gen) { __nanosleep(64); }
        }
    }
    __syncthreads();
}

__global__ void __launch_bounds__(NTHR, 1)
fused_rcnn(const float* __restrict__ lg,
           const float* __restrict__ reg,
           const float* __restrict__ props,
           const float* __restrict__ ft,
           float* __restrict__ out_boxes,
           float* __restrict__ out_feats,
           int P, int FD) {
    // union: phase A stage buffer / phase D sort buffer
    __shared__ __align__(16) float s_buf[CHF];          // 46592 B
    unsigned long long* s_sort = (unsigned long long*)s_buf;  // CAP*8 = 32768 B
    __shared__ unsigned s_tu[BIMG];

    const int tid  = threadIdx.x;
    const int bid  = blockIdx.x;
    const int wid  = tid >> 5;
    const int lane = tid & 31;
    const int N    = BIMG * P;
    const float NEG = __int_as_float(0xff800000);  // -inf

    // ============ Phase A: chunked smem-transposed softmax stats ============
    {
        const int nchunk = N / CHROWS;
        const int r = tid >> 3;       // row within chunk 0..127
        const int j = tid & 7;        // column-group lane 0..7
        for (int chunk = bid; chunk < nchunk; chunk += NBLK) {
            // stage 128 rows coalesced as float4
            const float4* src = (const float4*)(lg + (long)chunk * CHF);
            float4* dst4 = (float4*)s_buf;
            #pragma unroll
            for (int i = 0; i < 3; i++) {
                int k = tid + i * NTHR;
                if (k < CHF4) dst4[k] = src[k];
            }
            __syncthreads();

            // 8 threads per row scan columns j, j+8, ...
            const float* rp = s_buf + r * NC;
            float s0 = 0.f, s1 = 0.f, cm = NEG;
            #pragma unroll
            for (int k = 0; k < 12; k++) {
                int c = j + (k << 3);
                if (c < NC) {
                    float v = rp[c];
                    float e = __expf(v);
                    if (k & 1) s1 += e; else s0 += e;
                    if (c >= 1) cm = fmaxf(cm, v);
                }
            }
            float s = s0 + s1;
            #pragma unroll
            for (int o = 1; o < 8; o <<= 1) {
                s  += __shfl_xor_sync(~0u, s, o);
                cm  = fmaxf(cm, __shfl_xor_sync(~0u, cm, o));
            }
            if (j == 0) {
                int row = chunk * CHROWS + r;
                float ko = __logf(s);
                g_keyoff[row] = ko;
                unsigned u = f2sort(cm - ko);
                g_cksort[row] = u;
                atomicAdd(&g_hist[row / P][u >> 20], 1u);
            }
            __syncthreads();
        }
    }

    grid_barrier();

    // ============ Phase B: per-block redundant rank-100 threshold ============
    // keys strictly negative -> sortable codes < 0x80000000 -> bins < 2048
    if (wid < BIMG) {
        const int im = wid;
        const unsigned* hb = g_hist[im];
        unsigned part = 0;
        #pragma unroll
        for (int k = 0; k < 64; k++) part += hb[(lane << 6) + k];
        unsigned sfx = part;  // inclusive suffix sum toward lane 31
        #pragma unroll
        for (int o = 1; o < 32; o <<= 1) {
            unsigned t = __shfl_down_sync(~0u, sfx, o);
            if (lane + o < 32) sfx += t;
        }
        unsigned bal = __ballot_sync(~0u, sfx >= DET);
        int lstar = 31 - __clz(bal);                     // total >= 4096 so bal != 0
        unsigned nxt = __shfl_sync(~0u, sfx, (lstar + 1) & 31);
        unsigned above = (lstar < 31) ? nxt : 0u;        // count in lanes > lstar
        int base = lstar << 6;
        unsigned tu = 0, run = above;
        #pragma unroll
        for (int h = 1; h >= 0; h--) {
            unsigned v = hb[base + (h << 5) + lane];
            unsigned s2 = v;
            #pragma unroll
            for (int o = 1; o < 32; o <<= 1) {
                unsigned t = __shfl_down_sync(~0u, s2, o);
                if (lane + o < 32) s2 += t;
            }
            unsigned tot = __shfl_sync(~0u, s2, 0);
            if (run + tot >= DET) {
                unsigned b2 = __ballot_sync(~0u, run + s2 >= DET);
                int l2 = 31 - __clz(b2);
                tu = ((unsigned)(base + (h << 5) + l2)) << 20;
                break;
            }
            run += tot;
        }
        if (lane == 0) s_tu[im] = tu;
    }
    __syncthreads();

    // ============ Phase C: candidate filter (1 thread/proposal, row early-exit) ====
    {
        int g = bid * NTHR + tid;
        if (g < N) {
            int img = g / P;
            unsigned TU = s_tu[img];
            if (g_cksort[g] >= TU) {
                int   pl = g - img * P;
                float ko = g_keyoff[g];
                const float* row = lg + (long)g * NC;
                #pragma unroll 10
                for (int c = 1; c < NC; c++) {
                    float v = __ldg(row + c);
                    unsigned su = f2sort(v - ko);
                    if (su >= TU) {
                        unsigned idx = (unsigned)(pl * CM1 + (c - 1));
                        unsigned pos = atomicAdd(&g_cnt[img], 1u);
                        if (pos < CAP)
                            g_cand[img][pos] = ((unsigned long long)(~su) << 32) | idx;
                    }
                }
            }
        }
    }

    grid_barrier();

    // ============ Phase D: per-image sort + box decode (blocks 0..7) ============
    if (bid < BIMG) {
        const int img = bid;
        int n = (int)min(g_cnt[img], (unsigned)CAP);
        int m = 128; while (m < n) m <<= 1;
        for (int i = tid; i < m; i += NTHR)
            s_sort[i] = (i < n) ? g_cand[img][i] : ~0ULL;
        __syncthreads();
        for (int k = 2; k <= m; k <<= 1)
            for (int jj = k >> 1; jj > 0; jj >>= 1) {
                for (int i = tid; i < m; i += NTHR) {
                    int ixj = i ^ jj;
                    if (ixj > i) {
                        unsigned long long a = s_sort[i], b = s_sort[ixj];
                        bool up = ((i & k) == 0);
                        if ((a > b) == up) { s_sort[i] = b; s_sort[ixj] = a; }
                    }
                }
                __syncthreads();
            }
        if (tid < DET) {
            unsigned idx = (unsigned)(s_sort[tid] & 0xffffffffu);
            int p = idx / CM1;
            int c = idx % CM1 + 1;
            long gp = (long)img * P + p;
            const float* pr = props + gp * 4;
            float x1 = pr[0], y1 = pr[1], x2 = pr[2], y2 = pr[3];
            float w = x2 - x1, h = y2 - y1;
            float cx = x1 + 0.5f * w, cy = y1 + 0.5f * h;
            const float* rr = reg + gp * (4 * NC) + 4 * c;
            const float CLIP = 4.135166556742356f;  // log(1000/16)
            float dx = rr[0] / 10.0f, dy = rr[1] / 10.0f;
            float dw = fminf(rr[2] / 5.0f, CLIP);
            float dh = fminf(rr[3] / 5.0f, CLIP);
            float pcx = dx * w + cx, pcy = dy * h + cy;
            float pw = expf(dw) * w, ph = expf(dh) * h;
            float bx1 = pcx - 0.5f * pw, by1 = pcy - 0.5f * ph;
            float bx2 = pcx + 0.5f * pw, by2 = pcy + 0.5f * ph;
            bx1 = fminf(fmaxf(bx1, 0.f), 800.f);
            bx2 = fminf(fmaxf(bx2, 0.f), 800.f);
            by1 = fminf(fmaxf(by1, 0.f), 800.f);
            by2 = fminf(fmaxf(by2, 0.f), 800.f);
            float* o = out_boxes + ((long)img * DET + tid) * 4;
            o[0] = bx1 / 800.f; o[1] = by1 / 800.f;
            o[2] = bx2 / 800.f; o[3] = by2 / 800.f;
            g_selp[img][tid] = p;
        }
        __syncthreads();
        if (tid == 0) g_cnt[img] = 0;   // reset for next graph replay
    }

    grid_barrier();

    // ============ Phase E: feature gather (flat float4 copy) + scratch reset ====
    {
        const int FD4 = FD >> 2;                     // 256
        const long total4 = (long)BIMG * DET * FD4;  // 204800
        const int gtid = bid * NTHR + tid;
        const int nthr = NBLK * NTHR;
        for (long i = gtid; i < total4; i += nthr) {
            int  col = (int)(i & (FD4 - 1));
            int  det = (int)(i >> 8);                // FD4 == 256
            int  b   = det / DET;
            int  r   = det - b * DET;
            int  p   = g_selp[b][r];
            const float4* src = (const float4*)(ft + ((long)b * P + p) * FD);
            float4* dst = (float4*)(out_feats + (long)det * FD);
            dst[col] = src[col];
        }
        for (int i = gtid; i < BIMG * NBINS; i += nthr)
            ((unsigned*)g_hist)[i] = 0u;
    }
}

extern "C" void kernel_launch(void* const* d_in, const int* in_sizes, int n_in,
                              void* d_out, int out_size) {
    const float* lg    = (const float*)d_in[0];
    const float* reg   = (const float*)d_in[1];
    const float* props = (const float*)d_in[2];
    const float* ft    = (const float*)d_in[3];
    int N  = in_sizes[0] / NC;     // 32768
    int P  = N / BIMG;             // 4096
    int FD = in_sizes[3] / N;      // 1024
    float* out_boxes = (float*)d_out;
    float* out_feats = out_boxes + (long)BIMG * DET * 4;

    fused_rcnn<<<NBLK, NTHR>>>(lg, reg, props, ft, out_boxes, out_feats, P, FD);
}

// round 6
// speedup vs baseline: 1.1292x; 1.1292x over previous
#include <cuda_runtime.h>

#define NC    91
#define CM1   90
#define BIMG  8
#define DET   100
#define NBINS 4096
#define CAP   4096
#define MAXP  4096
#define MAXN  (BIMG*MAXP)
#define NBLK  148
#define NTHR  1024
#define NWRP  (NTHR/32)
#define DBINS 2048
#define CAPL  512

// ---------- scratch (static device globals) ----------
__device__ float    g_keyoff[MAXN];
__device__ unsigned g_cksort[MAXN];
__device__ unsigned g_hist[BIMG][NBINS];
__device__ unsigned g_cnt[BIMG];
__device__ unsigned long long g_cand[BIMG][CAP];
__device__ unsigned g_bar_cnt;
__device__ unsigned g_bar_gen;

__device__ __forceinline__ unsigned f2sort(float x) {
    unsigned u = __float_as_uint(x);
    return (u & 0x80000000u) ? ~u : (u | 0x80000000u);
}

__device__ __forceinline__ void grid_barrier() {
    __syncthreads();
    if (threadIdx.x == 0) {
        __threadfence();
        unsigned gen = *((volatile unsigned*)&g_bar_gen);
        unsigned arrived = atomicAdd(&g_bar_cnt, 1u);
        if (arrived == (unsigned)(gridDim.x - 1)) {
            g_bar_cnt = 0;
            __threadfence();
            atomicExch(&g_bar_gen, gen + 1u);
        } else {
            while (*((volatile unsigned*)&g_bar_gen) == gen) { __nanosleep(64); }
        }
    }
    __syncthreads();
}

__device__ __forceinline__ void bitonic(unsigned long long* a, int m, int tid) {
    for (int k = 2; k <= m; k <<= 1)
        for (int j = k >> 1; j > 0; j >>= 1) {
            for (int i = tid; i < m; i += NTHR) {
                int ixj = i ^ j;
                if (ixj > i) {
                    unsigned long long x = a[i], y = a[ixj];
                    bool up = ((i & k) == 0);
                    if ((x > y) == up) { a[i] = y; a[ixj] = x; }
                }
            }
            __syncthreads();
        }
}

__global__ void __launch_bounds__(NTHR, 1)
fused_rcnn(const float* __restrict__ lg,
           const float* __restrict__ reg,
           const float* __restrict__ props,
           const float* __restrict__ ft,
           float* __restrict__ out_boxes,
           float* __restrict__ out_feats,
           int P, int FD) {
    __shared__ __align__(16) unsigned long long s_sort[CAP];  // 32 KB (phase D)
    __shared__ __align__(16) unsigned s_u[DBINS];             // 8 KB: C worklist / D hist+list
    __shared__ unsigned s_tu[BIMG];
    __shared__ int s_p[DET];
    __shared__ int s_c0, s_cutB, s_lcnt;

    const int tid  = threadIdx.x;
    const int bid  = blockIdx.x;
    const int wid  = tid >> 5;
    const int lane = tid & 31;
    const int N    = BIMG * P;
    const float NEG = __int_as_float(0xff800000);  // -inf

    // ============ Phase A: warp-per-row softmax stats (2-row unroll) ============
    {
        const int gwarp = bid * NWRP + wid;
        const int nw = NBLK * NWRP;
        const bool has2 = lane < NC - 64;   // lane+64 < 91
        for (int g = gwarp; g < N; g += 2 * nw) {
            int g2 = g + nw;
            bool hasB = (g2 < N);
            const float* rA = lg + (long)g * NC;
            const float* rB = lg + (long)(hasB ? g2 : g) * NC;
            float a0 = rA[lane], a1 = rA[lane + 32];
            float a2 = has2 ? rA[lane + 64] : 0.f;
            float b0 = rB[lane], b1 = rB[lane + 32];
            float b2 = has2 ? rB[lane + 64] : 0.f;

            float sA = __expf(a0) + __expf(a1) + (has2 ? __expf(a2) : 0.f);
            float cA = fmaxf((lane >= 1) ? a0 : NEG, fmaxf(a1, has2 ? a2 : NEG));
            float sB = __expf(b0) + __expf(b1) + (has2 ? __expf(b2) : 0.f);
            float cB = fmaxf((lane >= 1) ? b0 : NEG, fmaxf(b1, has2 ? b2 : NEG));
            #pragma unroll
            for (int o = 16; o; o >>= 1) {
                sA += __shfl_xor_sync(~0u, sA, o);
                cA  = fmaxf(cA, __shfl_xor_sync(~0u, cA, o));
                sB += __shfl_xor_sync(~0u, sB, o);
                cB  = fmaxf(cB, __shfl_xor_sync(~0u, cB, o));
            }
            if (lane == 0) {
                float ko = __logf(sA);
                g_keyoff[g] = ko;
                unsigned u = f2sort(cA - ko);
                g_cksort[g] = u;
                atomicAdd(&g_hist[g / P][u >> 20], 1u);
                if (hasB) {
                    float ko2 = __logf(sB);
                    g_keyoff[g2] = ko2;
                    unsigned u2 = f2sort(cB - ko2);
                    g_cksort[g2] = u2;
                    atomicAdd(&g_hist[g2 / P][u2 >> 20], 1u);
                }
            }
        }
    }

    grid_barrier();

    // ============ Phase B: rank-100 coarse threshold (blocks < 32, redundant) ============
    if (bid < 32 && wid < BIMG) {
        const int im = wid;
        const unsigned* hb = g_hist[im];
        unsigned part = 0;
        #pragma unroll
        for (int k = 0; k < 64; k++) part += hb[(lane << 6) + k];
        unsigned sfx = part;  // inclusive suffix sum toward lane 31
        #pragma unroll
        for (int o = 1; o < 32; o <<= 1) {
            unsigned t = __shfl_down_sync(~0u, sfx, o);
            if (lane + o < 32) sfx += t;
        }
        unsigned bal = __ballot_sync(~0u, sfx >= DET);
        int lstar = 31 - __clz(bal);
        unsigned nxt = __shfl_sync(~0u, sfx, (lstar + 1) & 31);
        unsigned above = (lstar < 31) ? nxt : 0u;
        int base = lstar << 6;
        unsigned tu = 0, run = above;
        #pragma unroll
        for (int h = 1; h >= 0; h--) {
            unsigned v = hb[base + (h << 5) + lane];
            unsigned s2 = v;
            #pragma unroll
            for (int o = 1; o < 32; o <<= 1) {
                unsigned t = __shfl_down_sync(~0u, s2, o);
                if (lane + o < 32) s2 += t;
            }
            unsigned tot = __shfl_sync(~0u, s2, 0);
            if (run + tot >= DET) {
                unsigned b2 = __ballot_sync(~0u, run + s2 >= DET);
                int l2 = 31 - __clz(b2);
                tu = ((unsigned)(base + (h << 5) + l2)) << 20;
                break;
            }
            run += tot;
        }
        if (lane == 0) s_tu[im] = tu;
    }
    __syncthreads();

    // ============ Phase C: worklist + warp-per-survivor filter ============
    {
        const int base = bid * NTHR;
        if (base < N) {                    // blocks 0..31
            const int img = base / P;      // block lies within one image (P % NTHR == 0)
            const int pbase = base - img * P;
            unsigned TU = s_tu[img];
            float Tf = __uint_as_float(~TU);   // s2f(TU): TU < 0x80000000 (keys negative)
            if (tid == 0) s_c0 = 0;
            __syncthreads();
            int g = base + tid;
            if (g_cksort[g] >= TU) {
                int pos = atomicAdd(&s_c0, 1);
                ((int*)s_u)[pos] = tid;
            }
            __syncthreads();
            int ln = s_c0;
            const bool has2 = lane < NC - 64;
            for (int i = wid; i < ln; i += NWRP) {
                int loc = ((int*)s_u)[i];
                int row = base + loc;
                float ko = g_keyoff[row];
                const float* rp = lg + (long)row * NC;
                float v0 = rp[lane], v1 = rp[lane + 32];
                float v2 = has2 ? rp[lane + 64] : 0.f;
                float d0 = v0 - ko, d1 = v1 - ko, d2 = v2 - ko;
                int pl = pbase + loc;
                // class index c: lane (skip c=0), lane+32, lane+64
                if (lane >= 1 && d0 >= Tf) {
                    unsigned pos = atomicAdd(&g_cnt[img], 1u);
                    if (pos < CAP)
                        g_cand[img][pos] = ((unsigned long long)(~f2sort(d0)) << 32)
                                           | (unsigned)(pl * CM1 + (lane - 1));
                }
                if (d1 >= Tf) {
                    unsigned pos = atomicAdd(&g_cnt[img], 1u);
                    if (pos < CAP)
                        g_cand[img][pos] = ((unsigned long long)(~f2sort(d1)) << 32)
                                           | (unsigned)(pl * CM1 + (lane + 31));
                }
                if (has2 && d2 >= Tf) {
                    unsigned pos = atomicAdd(&g_cnt[img], 1u);
                    if (pos < CAP)
                        g_cand[img][pos] = ((unsigned long long)(~f2sort(d2)) << 32)
                                           | (unsigned)(pl * CM1 + (lane + 63));
                }
            }
        }
    }

    grid_barrier();

    // ============ Phase D+E: per-image select + sort + decode + gather (blocks 0..7) ======
    if (bid < BIMG) {
        const int img = bid;
        int n = (int)min(g_cnt[img], (unsigned)CAP);
        for (int i = tid; i < n; i += NTHR) s_sort[i] = g_cand[img][i];
        for (int i = tid; i < DBINS; i += NTHR) s_u[i] = 0;
        __syncthreads();
        for (int i = tid; i < n; i += NTHR)
            atomicAdd(&s_u[(unsigned)(s_sort[i] >> 53)], 1u);
        __syncthreads();
        // cutoff bucket: smallest B with cumulative count >= DET (warp 0)
        if (wid == 0) {
            if (lane == 0) s_cutB = DBINS - 1;
            unsigned cum = 0;
            for (int bp = 0; bp < DBINS; bp += 32) {
                unsigned v = s_u[bp + lane];
                unsigned pf = v;  // inclusive prefix from lane 0
                #pragma unroll
                for (int o = 1; o < 32; o <<= 1) {
                    unsigned t = __shfl_up_sync(~0u, pf, o);
                    if (lane >= o) pf += t;
                }
                unsigned tot = __shfl_sync(~0u, pf, 31);
                if (cum + tot >= DET) {
                    unsigned bal = __ballot_sync(~0u, cum + pf >= DET);
                    int l = __ffs(bal) - 1;
                    if (lane == 0) s_cutB = bp + l;
                    break;
                }
                cum += tot;
            }
        }
        if (tid == 0) s_lcnt = 0;
        __syncthreads();
        unsigned cutB = (unsigned)s_cutB;
        unsigned long long* s_list = (unsigned long long*)s_u;  // hist no longer needed
        for (int i = tid; i < n; i += NTHR) {
            unsigned long long key = s_sort[i];
            if ((unsigned)(key >> 53) <= cutB) {
                int pos = atomicAdd(&s_lcnt, 1);
                if (pos < CAPL) s_list[pos] = key;
            }
        }
        __syncthreads();
        int ln = s_lcnt;
        unsigned long long* res;
        if (ln <= CAPL) {
            int m = 128; while (m < ln) m <<= 1;
            for (int i = tid; i < m; i += NTHR) if (i >= ln) s_list[i] = ~0ULL;
            __syncthreads();
            bitonic(s_list, m, tid);
            res = s_list;
        } else {
            int m = 128; while (m < n) m <<= 1;
            for (int i = tid; i < m; i += NTHR) if (i >= n) s_sort[i] = ~0ULL;
            __syncthreads();
            bitonic(s_sort, m, tid);
            res = s_sort;
        }
        if (tid < DET) {
            unsigned idx = (unsigned)(res[tid] & 0xffffffffu);
            int p = idx / CM1;
            int c = idx % CM1 + 1;
            long gp = (long)img * P + p;
            const float* pr = props + gp * 4;
            float x1 = pr[0], y1 = pr[1], x2 = pr[2], y2 = pr[3];
            float w = x2 - x1, h = y2 - y1;
            float cx = x1 + 0.5f * w, cy = y1 + 0.5f * h;
            const float* rr = reg + gp * (4 * NC) + 4 * c;
            const float CLIP = 4.135166556742356f;  // log(1000/16)
            float dx = rr[0] / 10.0f, dy = rr[1] / 10.0f;
            float dw = fminf(rr[2] / 5.0f, CLIP);
            float dh = fminf(rr[3] / 5.0f, CLIP);
            float pcx = dx * w + cx, pcy = dy * h + cy;
            float pw = expf(dw) * w, ph = expf(dh) * h;
            float bx1 = pcx - 0.5f * pw, by1 = pcy - 0.5f * ph;
            float bx2 = pcx + 0.5f * pw, by2 = pcy + 0.5f * ph;
            bx1 = fminf(fmaxf(bx1, 0.f), 800.f);
            bx2 = fminf(fmaxf(bx2, 0.f), 800.f);
            by1 = fminf(fmaxf(by1, 0.f), 800.f);
            by2 = fminf(fmaxf(by2, 0.f), 800.f);
            float* o = out_boxes + ((long)img * DET + tid) * 4;
            o[0] = bx1 / 800.f; o[1] = by1 / 800.f;
            o[2] = bx2 / 800.f; o[3] = by2 / 800.f;
            s_p[tid] = p;
        }
        __syncthreads();
        // gather this image's 100 feature rows
        {
            const int FD4 = FD >> 2;
            const int tot = DET * FD4;
            const float4* fsrc = (const float4*)(ft + (long)img * P * FD);
            float4* fdst = (float4*)(out_feats + (long)img * DET * FD);
            for (int i = tid; i < tot; i += NTHR) {
                int det = i / FD4, col = i - det * FD4;
                fdst[(long)det * FD4 + col] = fsrc[(long)s_p[det] * FD4 + col];
            }
        }
        if (tid == 0) g_cnt[img] = 0;  // reset for next replay
    } else if (bid >= BIMG) {
        // blocks 8..147: reset histogram for next replay, then exit
        unsigned* hf = (unsigned*)g_hist;
        for (int i = (bid - BIMG) * NTHR + tid; i < BIMG * NBINS; i += (NBLK - BIMG) * NTHR)
            hf[i] = 0u;
    }
}

extern "C" void kernel_launch(void* const* d_in, const int* in_sizes, int n_in,
                              void* d_out, int out_size) {
    const float* lg    = (const float*)d_in[0];
    const float* reg   = (const float*)d_in[1];
    const float* props = (const float*)d_in[2];
    const float* ft    = (const float*)d_in[3];
    int N  = in_sizes[0] / NC;     // 32768
    int P  = N / BIMG;             // 4096
    int FD = in_sizes[3] / N;      // 1024
    float* out_boxes = (float*)d_out;
    float* out_feats = out_boxes + (long)BIMG * DET * 4;

    fused_rcnn<<<NBLK, NTHR>>>(lg, reg, props, ft, out_boxes, out_feats, P, FD);
}

// round 7
// speedup vs baseline: 1.3856x; 1.2271x over previous
#include <cuda_runtime.h>

#define NC    91
#define CM1   90
#define BIMG  8
#define DET   100
#define NBINS 4096
#define CAP   4096
#define MAXP  4096
#define MAXN  (BIMG*MAXP)
#define BPI   18                 // blocks per image
#define NBLK  (BIMG*BPI)         // 144
#define NTHR  1024
#define NWRP  (NTHR/32)
#define WPI   (BPI*NWRP)         // 576 warps per image
#define DBINS 2048
#define CAPL  512

// ---------- scratch (static device globals, zero-initialized) ----------
__device__ float    g_keyoff[MAXN];
__device__ unsigned g_cksort[MAXN];
__device__ unsigned g_hist[BIMG][NBINS];
__device__ unsigned g_cnt[BIMG];
__device__ unsigned long long g_cand[BIMG][CAP];
__device__ int      g_selp[BIMG][DET];
__device__ unsigned g_adone[BIMG];
__device__ unsigned g_cdone[BIMG];
__device__ unsigned g_dflag[BIMG];
__device__ unsigned g_edone[BIMG];

__device__ __forceinline__ unsigned f2sort(float x) {
    unsigned u = __float_as_uint(x);
    return (u & 0x80000000u) ? ~u : (u | 0x80000000u);
}
__device__ __forceinline__ float sort2f(unsigned u) {
    return __uint_as_float((u & 0x80000000u) ? (u ^ 0x80000000u) : ~u);
}
__device__ __forceinline__ void wait_ge(volatile unsigned* p, unsigned v) {
    while (*p < v) __nanosleep(32);
}

__device__ __forceinline__ void bitonic(unsigned long long* a, int m, int tid) {
    for (int k = 2; k <= m; k <<= 1)
        for (int j = k >> 1; j > 0; j >>= 1) {
            for (int i = tid; i < m; i += NTHR) {
                int ixj = i ^ j;
                if (ixj > i) {
                    unsigned long long x = a[i], y = a[ixj];
                    bool up = ((i & k) == 0);
                    if ((x > y) == up) { a[i] = y; a[ixj] = x; }
                }
            }
            __syncthreads();
        }
}

__global__ void __launch_bounds__(NTHR, 1)
fused_rcnn(const float* __restrict__ lg,
           const float* __restrict__ reg,
           const float* __restrict__ props,
           const float* __restrict__ ft,
           float* __restrict__ out_boxes,
           float* __restrict__ out_feats,
           int P, int FD) {
    __shared__ __align__(16) unsigned long long s_sort[CAP];  // 32 KB (D only)
    __shared__ __align__(16) unsigned s_u[DBINS];             // 8 KB (D hist / list)
    __shared__ unsigned s_TU;
    __shared__ int s_cutB, s_lcnt;

    const int tid  = threadIdx.x;
    const int bid  = blockIdx.x;
    const int wid  = tid >> 5;
    const int lane = tid & 31;
    const int img  = bid / BPI;
    const int j    = bid - img * BPI;
    const long ib  = (long)img * P;              // first global row of image
    const bool has2 = lane < (NC - 64);
    const float NEG = __int_as_float(0xff800000);

    // ================= Phase A: warp-per-row stats, software-pipelined =================
    {
        const int w0 = j * NWRP + wid;           // warp index within image, 0..575
        int r = w0;
        float c0 = 0.f, c1 = 0.f, c2 = 0.f;
        bool valid = (r < P);
        if (valid) {
            const float* rp = lg + (ib + r) * NC;
            c0 = rp[lane]; c1 = rp[lane + 32]; c2 = has2 ? rp[lane + 64] : 0.f;
        }
        while (valid) {
            int rn = r + WPI;
            bool vn = (rn < P);
            float n0 = 0.f, n1 = 0.f, n2 = 0.f;
            if (vn) {                             // prefetch next row while reducing current
                const float* rp = lg + (ib + rn) * NC;
                n0 = rp[lane]; n1 = rp[lane + 32]; n2 = has2 ? rp[lane + 64] : 0.f;
            }
            float s = __expf(c0) + __expf(c1) + (has2 ? __expf(c2) : 0.f);
            #pragma unroll
            for (int o = 16; o; o >>= 1) s += __shfl_xor_sync(~0u, s, o);
            unsigned u0 = (lane >= 1) ? f2sort(c0) : 0u;
            unsigned u1 = f2sort(c1);
            unsigned u2 = has2 ? f2sort(c2) : 0u;
            unsigned um = __reduce_max_sync(~0u, max(u0, max(u1, u2)));
            if (lane == 0) {
                float cm = sort2f(um);
                float ko = __logf(s);
                int row = (int)(ib + r);
                g_keyoff[row] = ko;
                unsigned u = f2sort(cm - ko);
                g_cksort[row] = u;
                atomicAdd(&g_hist[img][u >> 20], 1u);
            }
            c0 = n0; c1 = n1; c2 = n2; r = rn; valid = vn;
        }
        __threadfence();
        __syncthreads();
        if (tid == 0) atomicAdd(&g_adone[img], 1u);
        if (j >= 4) return;                       // helper blocks done
    }

    // ================= Phase C: filter 1024 rows (blocks j=0..3 of each image) =========
    {
        if (tid == 0) wait_ge(&g_adone[img], BPI);
        __syncthreads();
        __threadfence();

        const int rloc = j * NTHR + tid;          // proposal index within image
        unsigned ck = g_cksort[ib + rloc];
        float ko_t  = g_keyoff[ib + rloc];

        // warp 0: redundant rank-100 coarse threshold from histogram
        if (wid == 0) {
            const unsigned* hb = g_hist[img];
            unsigned part = 0;
            #pragma unroll
            for (int k = 0; k < 64; k++) part += hb[(lane << 6) + k];
            unsigned sfx = part;
            #pragma unroll
            for (int o = 1; o < 32; o <<= 1) {
                unsigned t = __shfl_down_sync(~0u, sfx, o);
                if (lane + o < 32) sfx += t;
            }
            unsigned bal = __ballot_sync(~0u, sfx >= DET);
            int lstar = 31 - __clz(bal);
            unsigned nxt = __shfl_sync(~0u, sfx, (lstar + 1) & 31);
            unsigned above = (lstar < 31) ? nxt : 0u;
            int base = lstar << 6;
            unsigned tu = 0, run = above;
            #pragma unroll
            for (int h = 1; h >= 0; h--) {
                unsigned v = hb[base + (h << 5) + lane];
                unsigned s2 = v;
                #pragma unroll
                for (int o = 1; o < 32; o <<= 1) {
                    unsigned t = __shfl_down_sync(~0u, s2, o);
                    if (lane + o < 32) s2 += t;
                }
                unsigned tot = __shfl_sync(~0u, s2, 0);
                if (run + tot >= DET) {
                    unsigned b2 = __ballot_sync(~0u, run + s2 >= DET);
                    int l2 = 31 - __clz(b2);
                    tu = ((unsigned)(base + (h << 5) + l2)) << 20;
                    break;
                }
                run += tot;
            }
            if (lane == 0) s_TU = tu;
        }
        __syncthreads();
        const unsigned TU = s_TU;
        const float Tf = __uint_as_float(~TU);    // keys strictly negative: bits(x)=~f2sort(x)

        unsigned mball = __ballot_sync(~0u, ck >= TU);
        while (mball) {
            int src = __ffs(mball) - 1;
            mball &= mball - 1;
            float ko = __shfl_sync(~0u, ko_t, src);
            int pl = j * NTHR + (wid << 5) + src; // survivor's in-image proposal index
            const float* rp = lg + (ib + pl) * NC;
            float v0 = rp[lane], v1 = rp[lane + 32];
            float v2 = has2 ? rp[lane + 64] : NEG;
            float d0 = v0 - ko, d1 = v1 - ko, d2 = v2 - ko;
            if (lane >= 1 && d0 >= Tf) {
                unsigned pos = atomicAdd(&g_cnt[img], 1u);
                if (pos < CAP)
                    g_cand[img][pos] = ((unsigned long long)(~f2sort(d0)) << 32)
                                       | (unsigned)(pl * CM1 + (lane - 1));
            }
            if (d1 >= Tf) {
                unsigned pos = atomicAdd(&g_cnt[img], 1u);
                if (pos < CAP)
                    g_cand[img][pos] = ((unsigned long long)(~f2sort(d1)) << 32)
                                       | (unsigned)(pl * CM1 + (lane + 31));
            }
            if (d2 >= Tf) {
                unsigned pos = atomicAdd(&g_cnt[img], 1u);
                if (pos < CAP)
                    g_cand[img][pos] = ((unsigned long long)(~f2sort(d2)) << 32)
                                       | (unsigned)(pl * CM1 + (lane + 63));
            }
        }
        __threadfence();
        __syncthreads();
        if (tid == 0) atomicAdd(&g_cdone[img], 1u);
    }

    // ================= Phase D: select + sort + decode (block j==0 only) ==============
    if (j == 0) {
        if (tid == 0) wait_ge(&g_cdone[img], 4u);
        __syncthreads();
        __threadfence();

        int n = (int)min(g_cnt[img], (unsigned)CAP);
        for (int i = tid; i < n; i += NTHR) s_sort[i] = g_cand[img][i];
        for (int i = tid; i < DBINS; i += NTHR) s_u[i] = 0;
        __syncthreads();
        for (int i = tid; i < n; i += NTHR)
            atomicAdd(&s_u[(unsigned)(s_sort[i] >> 53)], 1u);
        __syncthreads();
        if (wid == 0) {
            if (lane == 0) s_cutB = DBINS - 1;
            unsigned cum = 0;
            for (int bp = 0; bp < DBINS; bp += 32) {
                unsigned v = s_u[bp + lane];
                unsigned pf = v;
                #pragma unroll
                for (int o = 1; o < 32; o <<= 1) {
                    unsigned t = __shfl_up_sync(~0u, pf, o);
                    if (lane >= o) pf += t;
                }
                unsigned tot = __shfl_sync(~0u, pf, 31);
                if (cum + tot >= DET) {
                    unsigned bal = __ballot_sync(~0u, cum + pf >= DET);
                    int l = __ffs(bal) - 1;
                    if (lane == 0) s_cutB = bp + l;
                    break;
                }
                cum += tot;
            }
        }
        if (tid == 0) s_lcnt = 0;
        __syncthreads();
        unsigned cutB = (unsigned)s_cutB;
        unsigned long long* s_list = (unsigned long long*)s_u;
        for (int i = tid; i < n; i += NTHR) {
            unsigned long long key = s_sort[i];
            if ((unsigned)(key >> 53) <= cutB) {
                int pos = atomicAdd(&s_lcnt, 1);
                if (pos < CAPL) s_list[pos] = key;
            }
        }
        __syncthreads();
        int ln = s_lcnt;
        unsigned long long* res;
        if (ln <= CAPL) {
            int m = 128; while (m < ln) m <<= 1;
            for (int i = tid; i < m; i += NTHR) if (i >= ln) s_list[i] = ~0ULL;
            __syncthreads();
            bitonic(s_list, m, tid);
            res = s_list;
        } else {
            int m = 128; while (m < n) m <<= 1;
            for (int i = tid; i < m; i += NTHR) if (i >= n) s_sort[i] = ~0ULL;
            __syncthreads();
            bitonic(s_sort, m, tid);
            res = s_sort;
        }
        if (tid < DET) {
            unsigned idx = (unsigned)(res[tid] & 0xffffffffu);
            int p = idx / CM1;
            int c = idx % CM1 + 1;
            long gp = ib + p;
            const float* pr = props + gp * 4;
            float x1 = pr[0], y1 = pr[1], x2 = pr[2], y2 = pr[3];
            float w = x2 - x1, h = y2 - y1;
            float cx = x1 + 0.5f * w, cy = y1 + 0.5f * h;
            const float* rr = reg + gp * (4 * NC) + 4 * c;
            const float CLIP = 4.135166556742356f;  // log(1000/16)
            float dx = rr[0] / 10.0f, dy = rr[1] / 10.0f;
            float dw = fminf(rr[2] / 5.0f, CLIP);
            float dh = fminf(rr[3] / 5.0f, CLIP);
            float pcx = dx * w + cx, pcy = dy * h + cy;
            float pw = expf(dw) * w, ph = expf(dh) * h;
            float bx1 = pcx - 0.5f * pw, by1 = pcy - 0.5f * ph;
            float bx2 = pcx + 0.5f * pw, by2 = pcy + 0.5f * ph;
            bx1 = fminf(fmaxf(bx1, 0.f), 800.f);
            bx2 = fminf(fmaxf(bx2, 0.f), 800.f);
            by1 = fminf(fmaxf(by1, 0.f), 800.f);
            by2 = fminf(fmaxf(by2, 0.f), 800.f);
            float* o = out_boxes + ((long)img * DET + tid) * 4;
            o[0] = bx1 / 800.f; o[1] = by1 / 800.f;
            o[2] = bx2 / 800.f; o[3] = by2 / 800.f;
            g_selp[img][tid] = p;
        }
        if (tid == 0) g_cnt[img] = 0;   // only D reads g_cnt; safe to reset here
        __threadfence();
        __syncthreads();
        if (tid == 0) atomicExch(&g_dflag[img], 1u);
    }

    // ================= Phase E: feature gather, 25 rows per block (j=0..3) ============
    {
        if (tid == 0 && j != 0) wait_ge(&g_dflag[img], 1u);
        __syncthreads();
        __threadfence();

        const int FD4 = FD >> 2;
        const int tot = 25 * FD4;
        const float4* fsrc = (const float4*)(ft + ib * FD);
        float4* fdst = (float4*)(out_feats + ((long)img * DET + j * 25) * FD);
        const int* sp = &g_selp[img][j * 25];
        for (int i = tid; i < tot; i += NTHR) {
            int dr = i / FD4, col = i - dr * FD4;
            fdst[(long)dr * FD4 + col] = fsrc[(long)sp[dr] * FD4 + col];
        }
        // reset this block's quarter of the (used) histogram bins
        for (int i = tid; i < DBINS / 4; i += NTHR)
            g_hist[img][j * (DBINS / 4) + i] = 0u;
        __threadfence();
        __syncthreads();
        if (tid == 0) {
            unsigned pos = atomicAdd(&g_edone[img], 1u);
            if (pos == 3u) {       // last finisher resets per-image sync state
                g_adone[img] = 0u;
                g_cdone[img] = 0u;
                g_dflag[img] = 0u;
                g_edone[img] = 0u;
                __threadfence();
            }
        }
    }
}

extern "C" void kernel_launch(void* const* d_in, const int* in_sizes, int n_in,
                              void* d_out, int out_size) {
    const float* lg    = (const float*)d_in[0];
    const float* reg   = (const float*)d_in[1];
    const float* props = (const float*)d_in[2];
    const float* ft    = (const float*)d_in[3];
    int N  = in_sizes[0] / NC;     // 32768
    int P  = N / BIMG;             // 4096
    int FD = in_sizes[3] / N;      // 1024
    float* out_boxes = (float*)d_out;
    float* out_feats = out_boxes + (long)BIMG * DET * 4;

    fused_rcnn<<<NBLK, NTHR>>>(lg, reg, props, ft, out_boxes, out_feats, P, FD);
}

// round 9
// speedup vs baseline: 1.4554x; 1.0504x over previous
#include <cuda_runtime.h>

#define NC    91
#define CM1   90
#define BIMG  8
#define DET   100
#define NBINS 4096
#define CAP   4096
#define MAXP  4096
#define MAXN  (BIMG*MAXP)
#define BPI   18                 // blocks per image
#define NBLK  (BIMG*BPI)         // 144
#define NTHR  1024
#define NWRP  (NTHR/32)
#define WPI   (BPI*NWRP)         // 576 warps per image
#define DBINS 2048
#define CAPL  512
#define RCAP  2048

// ---------- scratch (static device globals, zero-initialized) ----------
__device__ unsigned long long g_rowinfo[MAXN];   // k1<<32 | (k2&~127)|cls
__device__ float    g_keyoff[MAXN];
__device__ unsigned g_hist[BIMG][NBINS];
__device__ int      g_selp[BIMG][DET];
__device__ unsigned g_adone[BIMG];
__device__ unsigned g_dflag[BIMG];
__device__ unsigned g_edone[BIMG];

__device__ __forceinline__ unsigned f2sort(float x) {
    unsigned u = __float_as_uint(x);
    return (u & 0x80000000u) ? ~u : (u | 0x80000000u);
}
__device__ __forceinline__ float sort2f(unsigned u) {
    return __uint_as_float((u & 0x80000000u) ? (u ^ 0x80000000u) : ~u);
}
__device__ __forceinline__ void wait_ge(volatile unsigned* p, unsigned v) {
    while (*p < v) __nanosleep(32);
}

__device__ __forceinline__ void bitonic(unsigned long long* a, int m, int tid) {
    for (int k = 2; k <= m; k <<= 1)
        for (int j = k >> 1; j > 0; j >>= 1) {
            for (int i = tid; i < m; i += NTHR) {
                int ixj = i ^ j;
                if (ixj > i) {
                    unsigned long long x = a[i], y = a[ixj];
                    bool up = ((i & k) == 0);
                    if ((x > y) == up) { a[i] = y; a[ixj] = x; }
                }
            }
            __syncthreads();
        }
}

__global__ void __launch_bounds__(NTHR, 1)
fused_rcnn(const float* __restrict__ lg,
           const float* __restrict__ reg,
           const float* __restrict__ props,
           const float* __restrict__ ft,
           float* __restrict__ out_boxes,
           float* __restrict__ out_feats,
           int P, int FD) {
    __shared__ __align__(16) unsigned long long s_sort[CAP];  // 32 KB
    __shared__ __align__(16) unsigned s_u[DBINS];             // 8 KB: rescan list / hist / list
    __shared__ unsigned s_TU;
    __shared__ int s_cutB, s_lcnt, s_n, s_nr;

    const int tid  = threadIdx.x;
    const int bid  = blockIdx.x;
    const int wid  = tid >> 5;
    const int lane = tid & 31;
    const int img  = bid / BPI;
    const int j    = bid - img * BPI;
    const long ib  = (long)img * P;
    const bool has2 = lane < (NC - 64);
    const float NEG = __int_as_float(0xff800000);

    // ========== Phase A: warp-per-row stats (sum + max/argmax/2nd-max), pipelined ==========
    {
        const int w0 = j * NWRP + wid;
        int r = w0;
        float c0 = 0.f, c1 = 0.f, c2 = 0.f;
        bool valid = (r < P);
        if (valid) {
            const float* rp = lg + (ib + r) * NC;
            c0 = rp[lane]; c1 = rp[lane + 32]; c2 = has2 ? rp[lane + 64] : 0.f;
        }
        while (valid) {
            int rn = r + WPI;
            bool vn = (rn < P);
            float n0 = 0.f, n1 = 0.f, n2 = 0.f;
            if (vn) {
                const float* rp = lg + (ib + rn) * NC;
                n0 = rp[lane]; n1 = rp[lane + 32]; n2 = has2 ? rp[lane + 64] : 0.f;
            }
            float s = __expf(c0) + __expf(c1) + (has2 ? __expf(c2) : 0.f);
            #pragma unroll
            for (int o = 16; o; o >>= 1) s += __shfl_xor_sync(~0u, s, o);

            // per-lane top-2 (strict > keeps smallest class on ties)
            unsigned u0p = (lane >= 1) ? f2sort(c0) : 0u;
            unsigned u1p = f2sort(c1);
            unsigned u2p = has2 ? f2sort(c2) : 0u;
            unsigned ua = u0p, ca = (unsigned)lane, ub;
            if (u1p > ua) { ub = ua; ua = u1p; ca = (unsigned)(lane + 32); }
            else          { ub = u1p; }
            if (u2p > ua) { ub = ua; ua = u2p; ca = (unsigned)(lane + 64); }
            else if (u2p > ub) ub = u2p;

            unsigned um   = __reduce_max_sync(~0u, ua);
            unsigned cand = (ua == um) ? ub : ua;
            unsigned smax = __reduce_max_sync(~0u, cand);
            bool multi    = __popc(__ballot_sync(~0u, ua == um)) > 1;
            unsigned k2r  = multi ? um : smax;
            unsigned cc   = (ua == um) ? ca : 1023u;
            unsigned cmin = __reduce_min_sync(~0u, cc);

            if (lane == 0) {
                float ko = __logf(s);
                unsigned k1 = f2sort(sort2f(um) - ko);
                unsigned lo = (k2r == 0u) ? cmin
                              : ((f2sort(sort2f(k2r) - ko) & ~127u) | cmin);
                long row = ib + r;
                g_rowinfo[row] = ((unsigned long long)k1 << 32) | lo;
                g_keyoff[row]  = ko;
                atomicAdd(&g_hist[img][k1 >> 20], 1u);
            }
            c0 = n0; c1 = n1; c2 = n2; r = rn; valid = vn;
        }
        __threadfence();
        __syncthreads();
        if (tid == 0) atomicAdd(&g_adone[img], 1u);
        if (j >= 4) return;
    }

    // ========== Phase D: select + sort + decode (block j==0 only) ==========
    if (j == 0) {
        if (tid == 0) wait_ge(&g_adone[img], BPI);
        __syncthreads();
        __threadfence();

        // --- TU: rank-100 coarse threshold from histogram (warp 0) ---
        if (wid == 0) {
            const unsigned* hb = g_hist[img];
            unsigned part = 0;
            #pragma unroll
            for (int k = 0; k < 64; k++) part += hb[(lane << 6) + k];
            unsigned sfx = part;
            #pragma unroll
            for (int o = 1; o < 32; o <<= 1) {
                unsigned t = __shfl_down_sync(~0u, sfx, o);
                if (lane + o < 32) sfx += t;
            }
            unsigned bal = __ballot_sync(~0u, sfx >= DET);
            int lstar = 31 - __clz(bal);
            unsigned nxt = __shfl_sync(~0u, sfx, (lstar + 1) & 31);
            unsigned above = (lstar < 31) ? nxt : 0u;
            int base = lstar << 6;
            unsigned tu = 0, run = above;
            #pragma unroll
            for (int h = 1; h >= 0; h--) {
                unsigned v = hb[base + (h << 5) + lane];
                unsigned s2 = v;
                #pragma unroll
                for (int o = 1; o < 32; o <<= 1) {
                    unsigned t = __shfl_down_sync(~0u, s2, o);
                    if (lane + o < 32) s2 += t;
                }
                unsigned tot = __shfl_sync(~0u, s2, 0);
                if (run + tot >= DET) {
                    unsigned b2 = __ballot_sync(~0u, run + s2 >= DET);
                    int l2 = 31 - __clz(b2);
                    tu = ((unsigned)(base + (h << 5) + l2)) << 20;
                    break;
                }
                run += tot;
            }
            if (lane == 0) s_TU = tu;
        }
        if (tid == 0) { s_n = 0; s_nr = 0; }
        __syncthreads();
        const unsigned TU = s_TU;
        const float Tf = __uint_as_float(~TU);   // sort2f(TU): keys strictly negative

        // --- scan rows: fast-push max-class candidates, queue rare rescans ---
        for (int r = tid; r < P; r += NTHR) {
            unsigned long long u = g_rowinfo[ib + r];
            unsigned k1 = (unsigned)(u >> 32);
            if (k1 >= TU) {
                unsigned lo = (unsigned)u;
                if (lo >= TU) {                       // second class may also qualify
                    int q = atomicAdd(&s_nr, 1);
                    if (q < RCAP) ((int*)s_u)[q] = r;
                } else {
                    unsigned cls = lo & 127u;
                    int q = atomicAdd(&s_n, 1);
                    if (q < CAP)
                        s_sort[q] = ((unsigned long long)(~k1) << 32)
                                    | (unsigned)(r * CM1 + (int)cls - 1);
                }
            }
        }
        __syncthreads();

        // --- rescan rows with >=2 qualifying classes (warp per row) ---
        {
            int nr = min(s_nr, RCAP);
            for (int i = wid; i < nr; i += NWRP) {
                int r = ((int*)s_u)[i];
                float ko = g_keyoff[ib + r];
                const float* rp = lg + (ib + r) * NC;
                float v0 = rp[lane], v1 = rp[lane + 32];
                float v2 = has2 ? rp[lane + 64] : NEG;
                float d0 = v0 - ko, d1 = v1 - ko, d2 = v2 - ko;
                if (lane >= 1 && d0 >= Tf) {
                    int q = atomicAdd(&s_n, 1);
                    if (q < CAP)
                        s_sort[q] = ((unsigned long long)(~f2sort(d0)) << 32)
                                    | (unsigned)(r * CM1 + (lane - 1));
                }
                if (d1 >= Tf) {
                    int q = atomicAdd(&s_n, 1);
                    if (q < CAP)
                        s_sort[q] = ((unsigned long long)(~f2sort(d1)) << 32)
                                    | (unsigned)(r * CM1 + (lane + 31));
                }
                if (d2 >= Tf) {
                    int q = atomicAdd(&s_n, 1);
                    if (q < CAP)
                        s_sort[q] = ((unsigned long long)(~f2sort(d2)) << 32)
                                    | (unsigned)(r * CM1 + (lane + 63));
                }
            }
        }
        __syncthreads();
        int n = min(s_n, CAP);

        // --- bucket-select to <=CAPL, then bitonic sort ---
        for (int i = tid; i < DBINS; i += NTHR) s_u[i] = 0;
        __syncthreads();
        for (int i = tid; i < n; i += NTHR)
            atomicAdd(&s_u[(unsigned)(s_sort[i] >> 53)], 1u);
        __syncthreads();
        if (wid == 0) {
            if (lane == 0) s_cutB = DBINS - 1;
            unsigned cum = 0;
            for (int bp = 0; bp < DBINS; bp += 32) {
                unsigned v = s_u[bp + lane];
                unsigned pf = v;
                #pragma unroll
                for (int o = 1; o < 32; o <<= 1) {
                    unsigned t = __shfl_up_sync(~0u, pf, o);
                    if (lane >= o) pf += t;
                }
                unsigned tot = __shfl_sync(~0u, pf, 31);
                if (cum + tot >= DET) {
                    unsigned bal = __ballot_sync(~0u, cum + pf >= DET);
                    int l = __ffs(bal) - 1;
                    if (lane == 0) s_cutB = bp + l;
                    break;
                }
                cum += tot;
            }
        }
        if (tid == 0) s_lcnt = 0;
        __syncthreads();
        unsigned cutB = (unsigned)s_cutB;
        unsigned long long* s_list = (unsigned long long*)s_u;
        for (int i = tid; i < n; i += NTHR) {
            unsigned long long key = s_sort[i];
            if ((unsigned)(key >> 53) <= cutB) {
                int pos = atomicAdd(&s_lcnt, 1);
                if (pos < CAPL) s_list[pos] = key;
            }
        }
        __syncthreads();
        int ln = s_lcnt;
        unsigned long long* res;
        if (ln <= CAPL) {
            int m = 128; while (m < ln) m <<= 1;
            for (int i = tid; i < m; i += NTHR) if (i >= ln) s_list[i] = ~0ULL;
            __syncthreads();
            bitonic(s_list, m, tid);
            res = s_list;
        } else {
            int m = 128; while (m < n) m <<= 1;
            for (int i = tid; i < m; i += NTHR) if (i >= n) s_sort[i] = ~0ULL;
            __syncthreads();
            bitonic(s_sort, m, tid);
            res = s_sort;
        }

        // --- decode top-100 boxes ---
        if (tid < DET) {
            unsigned idx = (unsigned)(res[tid] & 0xffffffffu);
            int p = idx / CM1;
            int c = idx % CM1 + 1;
            long gp = ib + p;
            const float* pr = props + gp * 4;
            float x1 = pr[0], y1 = pr[1], x2 = pr[2], y2 = pr[3];
            float w = x2 - x1, h = y2 - y1;
            float cx = x1 + 0.5f * w, cy = y1 + 0.5f * h;
            const float* rr = reg + gp * (4 * NC) + 4 * c;
            const float CLIP = 4.135166556742356f;  // log(1000/16)
            float dx = rr[0] / 10.0f, dy = rr[1] / 10.0f;
            float dw = fminf(rr[2] / 5.0f, CLIP);
            float dh = fminf(rr[3] / 5.0f, CLIP);
            float pcx = dx * w + cx, pcy = dy * h + cy;
            float pw = expf(dw) * w, ph = expf(dh) * h;
            float bx1 = pcx - 0.5f * pw, by1 = pcy - 0.5f * ph;
            float bx2 = pcx + 0.5f * pw, by2 = pcy + 0.5f * ph;
            bx1 = fminf(fmaxf(bx1, 0.f), 800.f);
            bx2 = fminf(fmaxf(bx2, 0.f), 800.f);
            by1 = fminf(fmaxf(by1, 0.f), 800.f);
            by2 = fminf(fmaxf(by2, 0.f), 800.f);
            float* o = out_boxes + ((long)img * DET + tid) * 4;
            o[0] = bx1 / 800.f; o[1] = by1 / 800.f;
            o[2] = bx2 / 800.f; o[3] = by2 / 800.f;
            g_selp[img][tid] = p;
        }
        __threadfence();
        __syncthreads();
        if (tid == 0) atomicExch(&g_dflag[img], 1u);
    }

    // ========== Phase E: feature gather, 25 rows per block (j=0..3) ==========
    {
        if (tid == 0 && j != 0) wait_ge(&g_dflag[img], 1u);
        __syncthreads();
        __threadfence();

        const int FD4 = FD >> 2;
        const int tot = 25 * FD4;
        const float4* fsrc = (const float4*)(ft + ib * FD);
        float4* fdst = (float4*)(out_feats + ((long)img * DET + j * 25) * FD);
        const int* sp = &g_selp[img][j * 25];
        for (int i = tid; i < tot; i += NTHR) {
            int dr = i / FD4, col = i - dr * FD4;
            fdst[(long)dr * FD4 + col] = fsrc[(long)sp[dr] * FD4 + col];
        }
        for (int i = tid; i < DBINS / 4; i += NTHR)
            g_hist[img][j * (DBINS / 4) + i] = 0u;
        __threadfence();
        __syncthreads();
        if (tid == 0) {
            unsigned pos = atomicAdd(&g_edone[img], 1u);
            if (pos == 3u) {
                g_adone[img] = 0u;
                g_dflag[img] = 0u;
                g_edone[img] = 0u;
                __threadfence();
            }
        }
    }
}

extern "C" void kernel_launch(void* const* d_in, const int* in_sizes, int n_in,
                              void* d_out, int out_size) {
    const float* lg    = (const float*)d_in[0];
    const float* reg   = (const float*)d_in[1];
    const float* props = (const float*)d_in[2];
    const float* ft    = (const float*)d_in[3];
    int N  = in_sizes[0] / NC;     // 32768
    int P  = N / BIMG;             // 4096
    int FD = in_sizes[3] / N;      // 1024
    float* out_boxes = (float*)d_out;
    float* out_feats = out_boxes + (long)BIMG * DET * 4;

    fused_rcnn<<<NBLK, NTHR>>>(lg, reg, props, ft, out_boxes, out_feats, P, FD);
}

// round 10
// speedup vs baseline: 1.5853x; 1.0892x over previous
#include <cuda_runtime.h>

#define NC    91
#define CM1   90
#define BIMG  8
#define DET   100
#define NBINS 4096
#define CAP   4096
#define MAXP  4096
#define MAXN  (BIMG*MAXP)
#define BPI   18                 // blocks per image
#define NBLK  (BIMG*BPI)         // 144
#define NTHR  1024
#define NWRP  (NTHR/32)
#define HPB   (NTHR/16)          // half-warps per block = 64
#define HPI   (BPI*HPB)          // 1152 half-warps per image
#define DBINS 2048
#define CAPL  512
#define RCAP  2048

// ---------- scratch (static device globals, zero-initialized) ----------
__device__ unsigned long long g_rowinfo[MAXN];   // k1<<32 | (k2&~127)|cls
__device__ float    g_keyoff[MAXN];
__device__ unsigned g_hist[BIMG][NBINS];
__device__ int      g_selp[BIMG][DET];
__device__ unsigned g_adone[BIMG];
__device__ unsigned g_dflag[BIMG];
__device__ unsigned g_edone[BIMG];

__device__ __forceinline__ unsigned f2sort(float x) {
    unsigned u = __float_as_uint(x);
    return (u & 0x80000000u) ? ~u : (u | 0x80000000u);
}
__device__ __forceinline__ float sort2f(unsigned u) {
    return __uint_as_float((u & 0x80000000u) ? (u ^ 0x80000000u) : ~u);
}
__device__ __forceinline__ void wait_ge(volatile unsigned* p, unsigned v) {
    while (*p < v) __nanosleep(32);
}

__device__ __forceinline__ void bitonic(unsigned long long* a, int m, int tid) {
    for (int k = 2; k <= m; k <<= 1)
        for (int j = k >> 1; j > 0; j >>= 1) {
            for (int i = tid; i < m; i += NTHR) {
                int ixj = i ^ j;
                if (ixj > i) {
                    unsigned long long x = a[i], y = a[ixj];
                    bool up = ((i & k) == 0);
                    if ((x > y) == up) { a[i] = y; a[ixj] = x; }
                }
            }
            __syncthreads();
        }
}

__global__ void __launch_bounds__(NTHR, 1)
fused_rcnn(const float* __restrict__ lg,
           const float* __restrict__ reg,
           const float* __restrict__ props,
           const float* __restrict__ ft,
           float* __restrict__ out_boxes,
           float* __restrict__ out_feats,
           int P, int FD) {
    __shared__ __align__(16) unsigned long long s_sort[CAP];  // 32 KB
    __shared__ __align__(16) unsigned s_u[DBINS];             // 8 KB: rescan list / hist / list
    __shared__ unsigned s_TU;
    __shared__ int s_cutB, s_lcnt, s_n, s_nr;

    const int tid  = threadIdx.x;
    const int bid  = blockIdx.x;
    const int wid  = tid >> 5;
    const int lane = tid & 31;
    const int img  = bid / BPI;
    const int j    = bid - img * BPI;
    const long ib  = (long)img * P;
    const bool has2 = lane < (NC - 64);
    const float NEG = __int_as_float(0xff800000);

    // ===== Phase A: half-warp-per-row stats (sum + max/argmax/2nd-max), pipelined =====
    {
        const int hw0 = j * HPB + (tid >> 4);    // half-warp index within image
        const int hl  = tid & 15;
        const bool h5 = hl < (NC - 80);          // hl+80 < 91

        int r = hw0;
        bool valid = (r < P);
        float c0=0.f,c1=0.f,c2=0.f,c3=0.f,c4=0.f,c5=0.f;
        if (valid) {
            const float* rp = lg + (ib + r) * NC;
            c0 = rp[hl];      c1 = rp[hl + 16]; c2 = rp[hl + 32];
            c3 = rp[hl + 48]; c4 = rp[hl + 64]; c5 = h5 ? rp[hl + 80] : 0.f;
        }
        while (valid) {
            int rn = r + HPI;
            bool vn = (rn < P);
            float n0=0.f,n1=0.f,n2=0.f,n3=0.f,n4=0.f,n5=0.f;
            if (vn) {                             // prefetch next row
                const float* rp = lg + (ib + rn) * NC;
                n0 = rp[hl];      n1 = rp[hl + 16]; n2 = rp[hl + 32];
                n3 = rp[hl + 48]; n4 = rp[hl + 64]; n5 = h5 ? rp[hl + 80] : 0.f;
            }
            float s = __expf(c0) + __expf(c1) + __expf(c2) + __expf(c3) + __expf(c4);
            if (h5) s += __expf(c5);

            // per-lane top-2 with class (ascending class order, strict > keeps min class)
            unsigned ua = (hl >= 1) ? f2sort(c0) : 0u;
            unsigned ca = (unsigned)hl, ub = 0u, u;
            u = f2sort(c1); if (u > ua) { ub = ua; ua = u; ca = (unsigned)(hl + 16); } else if (u > ub) ub = u;
            u = f2sort(c2); if (u > ua) { ub = ua; ua = u; ca = (unsigned)(hl + 32); } else if (u > ub) ub = u;
            u = f2sort(c3); if (u > ua) { ub = ua; ua = u; ca = (unsigned)(hl + 48); } else if (u > ub) ub = u;
            u = f2sort(c4); if (u > ua) { ub = ua; ua = u; ca = (unsigned)(hl + 64); } else if (u > ub) ub = u;
            if (h5) { u = f2sort(c5); if (u > ua) { ub = ua; ua = u; ca = (unsigned)(hl + 80); } else if (u > ub) ub = u; }

            // 4-step tree within the 16-lane group: sum + (max,cls,2nd) triple merge
            #pragma unroll
            for (int o = 1; o < 16; o <<= 1) {
                float    os = __shfl_xor_sync(~0u, s,  o, 16);
                unsigned oa = __shfl_xor_sync(~0u, ua, o, 16);
                unsigned oc = __shfl_xor_sync(~0u, ca, o, 16);
                unsigned ob = __shfl_xor_sync(~0u, ub, o, 16);
                s += os;
                if (oa > ua)       { ub = max(ua, ob); ua = oa; ca = oc; }
                else if (oa == ua) { ub = ua; ca = min(ca, oc); }
                else               { ub = max(ub, oa); }
            }

            if (hl == 0) {
                float ko = __logf(s);
                unsigned k1 = f2sort(sort2f(ua) - ko);
                unsigned lo = (ub == 0u) ? ca
                              : ((f2sort(sort2f(ub) - ko) & ~127u) | ca);
                long row = ib + r;
                g_rowinfo[row] = ((unsigned long long)k1 << 32) | lo;
                g_keyoff[row]  = ko;
                atomicAdd(&g_hist[img][k1 >> 20], 1u);
            }
            c0=n0; c1=n1; c2=n2; c3=n3; c4=n4; c5=n5; r = rn; valid = vn;
        }
        __threadfence();
        __syncthreads();
        if (tid == 0) atomicAdd(&g_adone[img], 1u);
        if (j >= 4) return;
    }

    // ========== Phase D: select + rank + decode (block j==0 only) ==========
    if (j == 0) {
        if (tid == 0) wait_ge(&g_adone[img], BPI);
        __syncthreads();
        __threadfence();

        // --- TU: rank-100 coarse threshold from histogram (warp 0) ---
        if (wid == 0) {
            const unsigned* hb = g_hist[img];
            unsigned part = 0;
            #pragma unroll
            for (int k = 0; k < 64; k++) part += hb[(lane << 6) + k];
            unsigned sfx = part;
            #pragma unroll
            for (int o = 1; o < 32; o <<= 1) {
                unsigned t = __shfl_down_sync(~0u, sfx, o);
                if (lane + o < 32) sfx += t;
            }
            unsigned bal = __ballot_sync(~0u, sfx >= DET);
            int lstar = 31 - __clz(bal);
            unsigned nxt = __shfl_sync(~0u, sfx, (lstar + 1) & 31);
            unsigned above = (lstar < 31) ? nxt : 0u;
            int base = lstar << 6;
            unsigned tu = 0, run = above;
            #pragma unroll
            for (int h = 1; h >= 0; h--) {
                unsigned v = hb[base + (h << 5) + lane];
                unsigned s2 = v;
                #pragma unroll
                for (int o = 1; o < 32; o <<= 1) {
                    unsigned t = __shfl_down_sync(~0u, s2, o);
                    if (lane + o < 32) s2 += t;
                }
                unsigned tot = __shfl_sync(~0u, s2, 0);
                if (run + tot >= DET) {
                    unsigned b2 = __ballot_sync(~0u, run + s2 >= DET);
                    int l2 = 31 - __clz(b2);
                    tu = ((unsigned)(base + (h << 5) + l2)) << 20;
                    break;
                }
                run += tot;
            }
            if (lane == 0) s_TU = tu;
        }
        if (tid == 0) { s_n = 0; s_nr = 0; }
        __syncthreads();
        const unsigned TU = s_TU;
        const float Tf = __uint_as_float(~TU);   // sort2f(TU): keys strictly negative

        // --- scan rows: fast-push max-class candidates, queue rare rescans ---
        for (int r = tid; r < P; r += NTHR) {
            unsigned long long u = g_rowinfo[ib + r];
            unsigned k1 = (unsigned)(u >> 32);
            if (k1 >= TU) {
                unsigned lo = (unsigned)u;
                if (lo >= TU) {                       // second class may also qualify
                    int q = atomicAdd(&s_nr, 1);
                    if (q < RCAP) ((int*)s_u)[q] = r;
                } else {
                    unsigned cls = lo & 127u;
                    int q = atomicAdd(&s_n, 1);
                    if (q < CAP)
                        s_sort[q] = ((unsigned long long)(~k1) << 32)
                                    | (unsigned)(r * CM1 + (int)cls - 1);
                }
            }
        }
        __syncthreads();

        // --- rescan rows with >=2 qualifying classes (warp per row) ---
        {
            int nr = min(s_nr, RCAP);
            for (int i = wid; i < nr; i += NWRP) {
                int r = ((int*)s_u)[i];
                float ko = g_keyoff[ib + r];
                const float* rp = lg + (ib + r) * NC;
                float v0 = rp[lane], v1 = rp[lane + 32];
                float v2 = has2 ? rp[lane + 64] : NEG;
                float d0 = v0 - ko, d1 = v1 - ko, d2 = v2 - ko;
                if (lane >= 1 && d0 >= Tf) {
                    int q = atomicAdd(&s_n, 1);
                    if (q < CAP)
                        s_sort[q] = ((unsigned long long)(~f2sort(d0)) << 32)
                                    | (unsigned)(r * CM1 + (lane - 1));
                }
                if (d1 >= Tf) {
                    int q = atomicAdd(&s_n, 1);
                    if (q < CAP)
                        s_sort[q] = ((unsigned long long)(~f2sort(d1)) << 32)
                                    | (unsigned)(r * CM1 + (lane + 31));
                }
                if (d2 >= Tf) {
                    int q = atomicAdd(&s_n, 1);
                    if (q < CAP)
                        s_sort[q] = ((unsigned long long)(~f2sort(d2)) << 32)
                                    | (unsigned)(r * CM1 + (lane + 63));
                }
            }
        }
        __syncthreads();
        int n = min(s_n, CAP);

        // --- bucket-select to <=CAPL ---
        for (int i = tid; i < DBINS; i += NTHR) s_u[i] = 0;
        __syncthreads();
        for (int i = tid; i < n; i += NTHR)
            atomicAdd(&s_u[(unsigned)(s_sort[i] >> 53)], 1u);
        __syncthreads();
        if (wid == 0) {
            if (lane == 0) s_cutB = DBINS - 1;
            unsigned cum = 0;
            for (int bp = 0; bp < DBINS; bp += 32) {
                unsigned v = s_u[bp + lane];
                unsigned pf = v;
                #pragma unroll
                for (int o = 1; o < 32; o <<= 1) {
                    unsigned t = __shfl_up_sync(~0u, pf, o);
                    if (lane >= o) pf += t;
                }
                unsigned tot = __shfl_sync(~0u, pf, 31);
                if (cum + tot >= DET) {
                    unsigned bal = __ballot_sync(~0u, cum + pf >= DET);
                    int l = __ffs(bal) - 1;
                    if (lane == 0) s_cutB = bp + l;
                    break;
                }
                cum += tot;
            }
        }
        if (tid == 0) s_lcnt = 0;
        __syncthreads();
        unsigned cutB = (unsigned)s_cutB;
        unsigned long long* s_list = (unsigned long long*)s_u;
        for (int i = tid; i < n; i += NTHR) {
            unsigned long long key = s_sort[i];
            if ((unsigned)(key >> 53) <= cutB) {
                int pos = atomicAdd(&s_lcnt, 1);
                if (pos < CAPL) s_list[pos] = key;
            }
        }
        __syncthreads();
        int ln = s_lcnt;
        unsigned long long* res;
        if (ln <= CAPL) {
            // --- rank-select: keys unique -> exact stable top-100 (no syncs in loop) ---
            if (tid < ln) {
                unsigned long long key = s_list[tid];
                int rank = 0;
                #pragma unroll 4
                for (int k = 0; k < ln; k++) rank += (s_list[k] < key);
                if (rank < DET) s_sort[rank] = key;
            }
            __syncthreads();
            res = s_sort;
        } else {
            int m = 128; while (m < n) m <<= 1;
            for (int i = tid; i < m; i += NTHR) if (i >= n) s_sort[i] = ~0ULL;
            __syncthreads();
            bitonic(s_sort, m, tid);
            res = s_sort;
        }

        // --- decode top-100 boxes ---
        if (tid < DET) {
            unsigned idx = (unsigned)(res[tid] & 0xffffffffu);
            int p = idx / CM1;
            int c = idx % CM1 + 1;
            long gp = ib + p;
            const float* pr = props + gp * 4;
            float x1 = pr[0], y1 = pr[1], x2 = pr[2], y2 = pr[3];
            float w = x2 - x1, h = y2 - y1;
            float cx = x1 + 0.5f * w, cy = y1 + 0.5f * h;
            const float* rr = reg + gp * (4 * NC) + 4 * c;
            const float CLIP = 4.135166556742356f;  // log(1000/16)
            float dx = rr[0] / 10.0f, dy = rr[1] / 10.0f;
            float dw = fminf(rr[2] / 5.0f, CLIP);
            float dh = fminf(rr[3] / 5.0f, CLIP);
            float pcx = dx * w + cx, pcy = dy * h + cy;
            float pw = expf(dw) * w, ph = expf(dh) * h;
            float bx1 = pcx - 0.5f * pw, by1 = pcy - 0.5f * ph;
            float bx2 = pcx + 0.5f * pw, by2 = pcy + 0.5f * ph;
            bx1 = fminf(fmaxf(bx1, 0.f), 800.f);
            bx2 = fminf(fmaxf(bx2, 0.f), 800.f);
            by1 = fminf(fmaxf(by1, 0.f), 800.f);
            by2 = fminf(fmaxf(by2, 0.f), 800.f);
            float* o = out_boxes + ((long)img * DET + tid) * 4;
            o[0] = bx1 / 800.f; o[1] = by1 / 800.f;
            o[2] = bx2 / 800.f; o[3] = by2 / 800.f;
            g_selp[img][tid] = p;
        }
        __threadfence();
        __syncthreads();
        if (tid == 0) atomicExch(&g_dflag[img], 1u);
    }

    // ========== Phase E: feature gather, 25 rows per block (j=0..3) ==========
    {
        if (tid == 0 && j != 0) wait_ge(&g_dflag[img], 1u);
        __syncthreads();
        __threadfence();

        const int FD4 = FD >> 2;
        const int tot = 25 * FD4;
        const float4* fsrc = (const float4*)(ft + ib * FD);
        float4* fdst = (float4*)(out_feats + ((long)img * DET + j * 25) * FD);
        const int* sp = &g_selp[img][j * 25];
        for (int i = tid; i < tot; i += NTHR) {
            int dr = i / FD4, col = i - dr * FD4;
            fdst[(long)dr * FD4 + col] = fsrc[(long)sp[dr] * FD4 + col];
        }
        for (int i = tid; i < DBINS / 4; i += NTHR)
            g_hist[img][j * (DBINS / 4) + i] = 0u;
        __threadfence();
        __syncthreads();
        if (tid == 0) {
            unsigned pos = atomicAdd(&g_edone[img], 1u);
            if (pos == 3u) {
                g_adone[img] = 0u;
                g_dflag[img] = 0u;
                g_edone[img] = 0u;
                __threadfence();
            }
        }
    }
}

extern "C" void kernel_launch(void* const* d_in, const int* in_sizes, int n_in,
                              void* d_out, int out_size) {
    const float* lg    = (const float*)d_in[0];
    const float* reg   = (const float*)d_in[1];
    const float* props = (const float*)d_in[2];
    const float* ft    = (const float*)d_in[3];
    int N  = in_sizes[0] / NC;     // 32768
    int P  = N / BIMG;             // 4096
    int FD = in_sizes[3] / N;      // 1024
    float* out_boxes = (float*)d_out;
    float* out_feats = out_boxes + (long)BIMG * DET * 4;

    fused_rcnn<<<NBLK, NTHR>>>(lg, reg, props, ft, out_boxes, out_feats, P, FD);
}